// round 13
// baseline (speedup 1.0000x reference)
#include <cuda_runtime.h>
#include <cuda_bf16.h>
#include <math.h>
#include <stdint.h>

#define NN 16384
#define MM 2000
#define MP 2048

#define UQ_OFF 0LL
#define UM_OFF 16777216LL
#define SQ_OFF 17801216LL
#define SMO_OFF 50569216LL
#define LS_OFF 83337216LL
#define UQ_BSTRIDE 1048576LL

// ---------------- scratch ---------------------------------------------------
__device__ __align__(16) float g_qf[(size_t)NN*512];
__device__ __align__(16) __nv_bfloat16 g_qf_h[(size_t)NN*512], g_qf_l[(size_t)NN*512];
__device__ __align__(16) __nv_bfloat16 g_kn_h[(size_t)MP*512], g_kn_l[(size_t)MP*512];
__device__ __align__(16) __nv_bfloat16 g_kT_h[(size_t)512*MP];
__device__ __align__(16) __nv_bfloat16 g_sm_h[(size_t)NN*MP];
__device__ __align__(16) float g_colsum[MM];
__device__ float g_colmaxE[MM];
__device__ __align__(16) float g_colinv[MM];
__device__ float g_denom[MM];
__device__ __align__(16) float g_qupd[(size_t)MM*512];
__device__ float g_loss[2];

// ---------------- helpers ---------------------------------------------------
__device__ __forceinline__ bool gt2(float va, int ia, float vb, int ib) {
    return va > vb || (va == vb && (unsigned)ia < (unsigned)ib);
}
__device__ __forceinline__ float block_reduce_sum256(float v, float* red) {
    int tid = threadIdx.x;
    red[tid] = v; __syncthreads();
    #pragma unroll
    for (int s = 128; s > 0; s >>= 1) { if (tid < s) red[tid] += red[tid + s]; __syncthreads(); }
    float r = red[0]; __syncthreads(); return r;
}
__device__ __forceinline__ void split2(float v, __nv_bfloat16& h, __nv_bfloat16& l) {
    h = __float2bfloat16(v);
    l = __float2bfloat16(v - __bfloat162float(h));
}
__device__ __forceinline__ uint32_t s2u(const void* p) {
    uint32_t a;
    asm("{ .reg .u64 t; cvta.to.shared.u64 t, %1; cvt.u32.u64 %0, t; }" : "=r"(a) : "l"(p));
    return a;
}
__device__ __forceinline__ void ldm_x4(uint32_t* r, uint32_t addr) {
    asm volatile("ldmatrix.sync.aligned.m8n8.x4.shared.b16 {%0,%1,%2,%3}, [%4];"
        : "=r"(r[0]), "=r"(r[1]), "=r"(r[2]), "=r"(r[3]) : "r"(addr));
}
__device__ __forceinline__ void mma16816(float* c, const uint32_t* a, const uint32_t* b) {
    asm volatile("mma.sync.aligned.m16n8k16.row.col.f32.bf16.bf16.f32 "
        "{%0,%1,%2,%3}, {%4,%5,%6,%7}, {%8,%9}, {%0,%1,%2,%3};"
        : "+f"(c[0]), "+f"(c[1]), "+f"(c[2]), "+f"(c[3])
        : "r"(a[0]), "r"(a[1]), "r"(a[2]), "r"(a[3]), "r"(b[0]), "r"(b[1]));
}
#define CPA(dst, src) asm volatile("cp.async.cg.shared.global [%0], [%1], 16;" :: "r"(dst), "l"(src))
#define CPC()  asm volatile("cp.async.commit_group;" ::: "memory")

// ---------------- K0: zero scratch ------------------------------------------
__global__ void k_zero() {
    int i = blockIdx.x * 256 + threadIdx.x;       // grid 1024
    if (i < 256000) ((float4*)g_qupd)[i] = make_float4(0.f, 0.f, 0.f, 0.f);
    if (i < MM) { g_denom[i] = 0.f; g_colsum[i] = 0.f; g_colmaxE[i] = 0.f; }
    if (i < 2)  g_loss[i] = 0.f;
    if (i < 12288) {
        ((uint32_t*)(g_kn_h + (size_t)MM * 512))[i] = 0u;
        ((uint32_t*)(g_kn_l + (size_t)MM * 512))[i] = 0u;
    }
}

// ---------------- K1: fused query prep ---------------------------------------
__global__ __launch_bounds__(256) void k_prep(const float* __restrict__ q,
                                              float* __restrict__ outb) {
    extern __shared__ float sm[];                 // [32][521]
    __shared__ float inv_s[32];
    int hw0 = blockIdx.x * 32, b = blockIdx.y;
    int tid = threadIdx.x, lane = tid & 31, w = tid >> 5;
    const float* qb = q + (size_t)b * 524288;

    for (int d = w; d < 512; d += 8)
        sm[lane * 521 + d] = qb[(size_t)d * 1024 + hw0 + lane];
    __syncthreads();

    #pragma unroll
    for (int rr = 0; rr < 4; rr++) {
        int r = w * 4 + rr;
        float s = 0.f;
        #pragma unroll
        for (int k = 0; k < 16; k++) { float v = sm[r * 521 + lane + 32 * k]; s += v * v; }
        #pragma unroll
        for (int off = 16; off > 0; off >>= 1) s += __shfl_xor_sync(~0u, s, off);
        if (lane == 0) inv_s[r] = 1.0f / fmaxf(sqrtf(s), 1e-12f);
    }
    __syncthreads();

    float* uq = outb + (size_t)b * UQ_BSTRIDE;
    for (int d = w; d < 512; d += 8)
        uq[(size_t)d * 1024 + hw0 + lane] = sm[lane * 521 + d] * inv_s[lane];

    #pragma unroll
    for (int rr = 0; rr < 4; rr++) {
        int r = w * 4 + rr;
        float iv = inv_s[r];
        size_t nbase = (size_t)(b * 1024 + hw0 + r) * 512;
        #pragma unroll
        for (int k = 0; k < 16; k++) {
            int d = lane + 32 * k;
            float v = sm[r * 521 + d] * iv;
            __nv_bfloat16 h, lo; split2(v, h, lo);
            g_qf[nbase + d] = v; g_qf_h[nbase + d] = h; g_qf_l[nbase + d] = lo;
        }
    }
}

// ---------------- K2: normalized keys bf16 split -----------------------------
__global__ void k_keynorm(const float* __restrict__ keys) {
    int m = blockIdx.x, tid = threadIdx.x;
    __shared__ float red[256];
    const float* kp = keys + (size_t)m * 512;
    float v0 = kp[tid], v1 = kp[tid + 256];
    float s = block_reduce_sum256(v0 * v0 + v1 * v1, red);
    float inv = 1.0f / fmaxf(sqrtf(s), 1e-12f);
    __nv_bfloat16 h, lo;
    split2(v0 * inv, h, lo);
    g_kn_h[(size_t)m * 512 + tid] = h; g_kn_l[(size_t)m * 512 + tid] = lo;
    split2(v1 * inv, h, lo);
    g_kn_h[(size_t)m * 512 + tid + 256] = h; g_kn_l[(size_t)m * 512 + tid + 256] = lo;
}

// ---------------- K2b: raw keys^T bf16 hi ------------------------------------
__global__ void k_keyT(const float* __restrict__ keys) {
    int m0 = blockIdx.x * 32, d0 = blockIdx.y * 32;
    int tx = threadIdx.x, ty = threadIdx.y;
    __shared__ float t[32][33];
    #pragma unroll
    for (int qq = 0; qq < 4; qq++) {
        int ml = ty + qq * 8, m = m0 + ml;
        t[ml][tx] = (m < MM) ? keys[(size_t)m * 512 + d0 + tx] : 0.f;
    }
    __syncthreads();
    #pragma unroll
    for (int qq = 0; qq < 4; qq++) {
        int dl = ty + qq * 8;
        g_kT_h[(size_t)(d0 + dl) * MP + m0 + tx] = __float2bfloat16(t[tx][dl]);
    }
}

// ---------------- HMMA GEMM: phase-separated MMA ordering --------------------
// MODE 0: E=exp(10*(qf@kn^T)) -> SQ + col sum/max   (3 products, phased)
// MODE 1: SM@keysT -> updated_query 2nd half         (1 product)
#define ROWB 80
#define AMATB 10240
#define BMATB 20480

template<int KTOT, int MODE>
__global__ __launch_bounds__(256, 1) void k_mma(float* __restrict__ outb) {
    constexpr int NA   = (MODE == 0) ? 2 : 1;
    constexpr int NB   = (MODE == 0) ? 2 : 1;
    constexpr int AOFF = NA * AMATB;
    constexpr int STGB = NA * AMATB + NB * BMATB;
    extern __shared__ char smc[];
    const uint32_t smb = s2u(smc);
    const int tid = threadIdx.x;
    const int lane = tid & 31, wid = tid >> 5;
    const int wr = wid & 1, wc = wid >> 1;
    const int i0 = blockIdx.x * 128, j0 = blockIdx.y * 256;

    const __nv_bfloat16* Ah = (MODE == 0) ? g_qf_h : g_sm_h;
    const __nv_bfloat16* Al = (MODE == 0) ? g_qf_l : g_sm_h;
    const __nv_bfloat16* Bh = (MODE == 0) ? g_kn_h : g_kT_h;
    const __nv_bfloat16* Bl = (MODE == 0) ? g_kn_l : g_kT_h;
    const int lda = (MODE == 0) ? 512 : MP;
    const int ldb = (MODE == 0) ? 512 : MP;

    float c[4][8][4];
    #pragma unroll
    for (int a = 0; a < 4; a++)
        #pragma unroll
        for (int b = 0; b < 8; b++)
            #pragma unroll
            for (int d = 0; d < 4; d++) c[a][b][d] = 0.f;

    const int NS = KTOT / 32;

    auto issue = [&](int stg, uint32_t dst0) {
        size_t k0 = (size_t)stg * 32;
        #pragma unroll
        for (int i = 0; i < NA * 2; i++) {
            int chunk = tid + 256 * i;
            int mat = chunk >> 9, row = (chunk >> 2) & 127, kc = chunk & 3;
            const __nv_bfloat16* p = mat ? Al : Ah;
            CPA(dst0 + mat * AMATB + row * ROWB + kc * 16, p + (size_t)(i0 + row) * lda + k0 + kc * 8);
        }
        #pragma unroll
        for (int i = 0; i < NB * 4; i++) {
            int chunk = tid + 256 * i;
            int mat = chunk >> 10, row = (chunk >> 2) & 255, kc = chunk & 3;
            const __nv_bfloat16* p = mat ? Bl : Bh;
            CPA(dst0 + AOFF + mat * BMATB + row * ROWB + kc * 16, p + (size_t)(j0 + row) * ldb + k0 + kc * 8);
        }
        CPC();
    };

    issue(0, smb);
    issue(1, smb + STGB);

    int buf = 0, pbuf = 2;
    for (int s = 0; s < NS; s++) {
        if (s == NS - 1) { asm volatile("cp.async.wait_group 0;" ::: "memory"); }
        else             { asm volatile("cp.async.wait_group 1;" ::: "memory"); }
        __syncthreads();
        if (s + 2 < NS) {
            issue(s + 2, smb + pbuf * STGB);
            pbuf = (pbuf == 2) ? 0 : pbuf + 1;
        }

        uint32_t sb = smb + buf * STGB;
        buf = (buf == 2) ? 0 : buf + 1;
        #pragma unroll
        for (int kh = 0; kh < 2; kh++) {
            const int k16 = kh * 16;
            uint32_t afh[4][4], afl[4][4], bfh[4][4], bfl[4][4];
            #pragma unroll
            for (int mt = 0; mt < 4; mt++) {
                uint32_t ad = sb + (uint32_t)(wr * 64 + mt * 16 + (lane & 15)) * ROWB
                            + (uint32_t)(k16 + ((lane >> 4) << 3)) * 2;
                ldm_x4(afh[mt], ad);
                if (MODE == 0) ldm_x4(afl[mt], ad + AMATB);
            }
            #pragma unroll
            for (int np = 0; np < 4; np++) {
                int n = wc * 64 + np * 16 + ((lane >> 4) << 3) + (lane & 7);
                int kk = k16 + (((lane >> 3) & 1) << 3);
                uint32_t bd = sb + AOFF + (uint32_t)n * ROWB + (uint32_t)kk * 2;
                ldm_x4(bfh[np], bd);
                if (MODE == 0) ldm_x4(bfl[np], bd + BMATB);
            }
            // Phase 1: hh — 32 MMAs, all-distinct accumulators
            #pragma unroll
            for (int mt = 0; mt < 4; mt++)
                #pragma unroll
                for (int np = 0; np < 4; np++) {
                    mma16816(c[mt][np * 2],     afh[mt], &bfh[np][0]);
                    mma16816(c[mt][np * 2 + 1], afh[mt], &bfh[np][2]);
                }
            if (MODE == 0) {
                // Phase 2: lh — same targets, 32 MMAs after their phase-1 writers
                #pragma unroll
                for (int mt = 0; mt < 4; mt++)
                    #pragma unroll
                    for (int np = 0; np < 4; np++) {
                        mma16816(c[mt][np * 2],     afl[mt], &bfh[np][0]);
                        mma16816(c[mt][np * 2 + 1], afl[mt], &bfh[np][2]);
                    }
                // Phase 3: hl
                #pragma unroll
                for (int mt = 0; mt < 4; mt++)
                    #pragma unroll
                    for (int np = 0; np < 4; np++) {
                        mma16816(c[mt][np * 2],     afh[mt], &bfl[np][0]);
                        mma16816(c[mt][np * 2 + 1], afh[mt], &bfl[np][2]);
                    }
            }
        }
    }
    __syncthreads();

    // ---------------- epilogue ----------------
    const int rbase = i0 + wr * 64 + (lane >> 2);
    const int cbase = j0 + wc * 64 + (lane & 3) * 2;
    if (MODE == 0) {
        float csum[8][2], cmax[8][2];
        #pragma unroll
        for (int nt = 0; nt < 8; nt++) { csum[nt][0] = csum[nt][1] = 0.f; cmax[nt][0] = cmax[nt][1] = 0.f; }
        #pragma unroll
        for (int mt = 0; mt < 4; mt++) {
            #pragma unroll
            for (int h2 = 0; h2 < 2; h2++) {
                int r = rbase + mt * 16 + h2 * 8;
                float* Erow = outb + SQ_OFF + (size_t)r * MM;
                #pragma unroll
                for (int nt = 0; nt < 8; nt++) {
                    int cc = cbase + nt * 8;
                    float2 e;
                    e.x = __expf(10.f * c[mt][nt][h2 * 2]);
                    e.y = __expf(10.f * c[mt][nt][h2 * 2 + 1]);
                    if (cc < MM) *(float2*)(Erow + cc) = e;
                    csum[nt][0] += e.x; csum[nt][1] += e.y;
                    cmax[nt][0] = fmaxf(cmax[nt][0], e.x);
                    cmax[nt][1] = fmaxf(cmax[nt][1], e.y);
                }
            }
        }
        #pragma unroll
        for (int off = 4; off < 32; off <<= 1) {
            #pragma unroll
            for (int nt = 0; nt < 8; nt++) {
                csum[nt][0] += __shfl_xor_sync(~0u, csum[nt][0], off);
                csum[nt][1] += __shfl_xor_sync(~0u, csum[nt][1], off);
                cmax[nt][0] = fmaxf(cmax[nt][0], __shfl_xor_sync(~0u, cmax[nt][0], off));
                cmax[nt][1] = fmaxf(cmax[nt][1], __shfl_xor_sync(~0u, cmax[nt][1], off));
            }
        }
        if ((lane >> 2) == 0) {
            #pragma unroll
            for (int nt = 0; nt < 8; nt++) {
                int col = cbase + nt * 8;
                if (col < MM) {
                    atomicAdd(&g_colsum[col], csum[nt][0]);
                    atomicMax((int*)&g_colmaxE[col], __float_as_int(cmax[nt][0]));
                    atomicAdd(&g_colsum[col + 1], csum[nt][1]);
                    atomicMax((int*)&g_colmaxE[col + 1], __float_as_int(cmax[nt][1]));
                }
            }
        }
    } else {
        #pragma unroll
        for (int mt = 0; mt < 4; mt++) {
            #pragma unroll
            for (int h2 = 0; h2 < 2; h2++) {
                int r = rbase + mt * 16 + h2 * 8;
                int bq = r >> 10, hw = r & 1023;
                float* base = outb + ((size_t)bq * 1024 + 512) * 1024 + hw;
                #pragma unroll
                for (int nt = 0; nt < 8; nt++) {
                    int cc = cbase + nt * 8;
                    base[(size_t)cc * 1024]       = c[mt][nt][h2 * 2];
                    base[(size_t)(cc + 1) * 1024] = c[mt][nt][h2 * 2 + 1];
                }
            }
        }
    }
}

__global__ void k_colinv() {
    int m = blockIdx.x * 256 + threadIdx.x;
    if (m < MM) g_colinv[m] = 1.0f / g_colsum[m];
}

// ---------------- K5: fused row pass (+ segment accumulate) ------------------
__global__ __launch_bounds__(256) void k_rows2(float* __restrict__ outb,
                                               const float* __restrict__ keys) {
    int n = blockIdx.x, tid = threadIdx.x, lane = tid & 31, w = tid >> 5;
    float* Er = outb + SQ_OFF  + (size_t)n * MM;
    float* Sr = outb + SMO_OFF + (size_t)n * MM;
    __shared__ float row[2000];
    __shared__ float sv1[8], sv2[8];
    __shared__ int   si1[8], si2[8];
    __shared__ float red[4][8];
    __shared__ float s_zs, s_wr;
    __shared__ int   s_g1, s_g2;

    float v1 = -3.0e38f, v2 = -3.0e38f; int i1 = 0x7FFFFFFF, i2 = 0x7FFFFFFF;
    float zs = 0.f;
    for (int m4 = tid; m4 < 500; m4 += 256) {
        float4 v = ((const float4*)Er)[m4];
        ((float4*)row)[m4] = v;
        zs += (v.x + v.y) + (v.z + v.w);
        float a[4] = {v.x, v.y, v.z, v.w};
        #pragma unroll
        for (int j = 0; j < 4; j++) {
            int m = m4 * 4 + j; float vv = a[j];
            if (gt2(vv, m, v1, i1)) { v2 = v1; i2 = i1; v1 = vv; i1 = m; }
            else if (gt2(vv, m, v2, i2)) { v2 = vv; i2 = m; }
        }
    }
    #pragma unroll
    for (int off = 16; off > 0; off >>= 1) {
        float w1 = __shfl_down_sync(~0u, v1, off); int j1 = __shfl_down_sync(~0u, i1, off);
        float w2 = __shfl_down_sync(~0u, v2, off); int j2 = __shfl_down_sync(~0u, i2, off);
        zs += __shfl_down_sync(~0u, zs, off);
        if (gt2(w1, j1, v1, i1)) {
            float o2; int p2;
            if (gt2(v1, i1, w2, j2)) { o2 = v1; p2 = i1; } else { o2 = w2; p2 = j2; }
            v1 = w1; i1 = j1; v2 = o2; i2 = p2;
        } else if (gt2(w1, j1, v2, i2)) { v2 = w1; i2 = j1; }
    }
    if (lane == 0) { sv1[w] = v1; si1[w] = i1; sv2[w] = v2; si2[w] = i2; red[0][w] = zs; }
    __syncthreads();
    if (tid == 0) {
        float b1 = sv1[0], b2 = sv2[0]; int c1 = si1[0], c2i = si2[0];
        #pragma unroll
        for (int k = 1; k < 8; k++) {
            float w1 = sv1[k], w2 = sv2[k]; int j1 = si1[k], j2 = si2[k];
            if (gt2(w1, j1, b1, c1)) {
                if (gt2(b1, c1, w2, j2)) { b2 = b1; c2i = c1; } else { b2 = w2; c2i = j2; }
                b1 = w1; c1 = j1;
            } else if (gt2(w1, j1, b2, c2i)) { b2 = w1; c2i = j1; }
        }
        s_g1 = c1; s_g2 = c2i;
        s_zs = ((red[0][0] + red[0][1]) + (red[0][2] + red[0][3]))
             + ((red[0][4] + red[0][5]) + (red[0][6] + red[0][7]));
        float ci = g_colinv[c1];
        float wr = (b1 * ci) / (g_colmaxE[c1] * ci + 1e-8f);
        s_wr = wr;
        atomicAdd(&g_denom[c1], wr);
    }
    __syncthreads();
    int gg1 = s_g1, gg2 = s_g2;
    float invZ = 1.0f / s_zs;
    float wr = s_wr;

    __nv_bfloat162* smh2 = (__nv_bfloat162*)(g_sm_h + (size_t)n * MP);
    for (int m4 = tid; m4 < 500; m4 += 256) {
        float4 e = ((const float4*)row)[m4];
        float4 sm4 = make_float4(e.x * invZ, e.y * invZ, e.z * invZ, e.w * invZ);
        ((float4*)Sr)[m4] = sm4;
        float4 ci = ((const float4*)g_colinv)[m4];
        ((float4*)Er)[m4] = make_float4(e.x * ci.x, e.y * ci.y, e.z * ci.z, e.w * ci.w);
        smh2[m4 * 2]     = __floats2bfloat162_rn(sm4.x, sm4.y);
        smh2[m4 * 2 + 1] = __floats2bfloat162_rn(sm4.z, sm4.w);
    }
    if (tid < 24) smh2[1000 + tid] = __floats2bfloat162_rn(0.f, 0.f);

    float c2 = 0.f, p2s = 0.f, n2s = 0.f;
    const float* qrow = g_qf + (size_t)n * 512;
    const float* k1 = keys + (size_t)gg1 * 512;
    const float* k2 = keys + (size_t)gg2 * 512;
    float* dst = g_qupd + (size_t)gg1 * 512;
    for (int d = tid; d < 512; d += 256) {
        float qv = qrow[d];
        float df = qv - k1[d];           c2 += df * df;
        float dp = df + 1e-6f;           p2s += dp * dp;
        float dn = (qv - k2[d]) + 1e-6f; n2s += dn * dn;
        atomicAdd(&dst[d], wr * qv);
    }
    #pragma unroll
    for (int off = 16; off > 0; off >>= 1) {
        c2  += __shfl_down_sync(~0u, c2,  off);
        p2s += __shfl_down_sync(~0u, p2s, off);
        n2s += __shfl_down_sync(~0u, n2s, off);
    }
    if (lane == 0) { red[1][w] = c2; red[2][w] = p2s; red[3][w] = n2s; }
    __syncthreads();
    if (tid == 0) {
        c2 = p2s = n2s = 0.f;
        #pragma unroll
        for (int k = 0; k < 8; k++) { c2 += red[1][k]; p2s += red[2][k]; n2s += red[3][k]; }
        atomicAdd(&g_loss[0], fmaxf(sqrtf(p2s) - sqrtf(n2s) + 1.0f, 0.0f));
        atomicAdd(&g_loss[1], c2);
    }
}

// ---------------- K8: updated_memory (+ finalize losses) ---------------------
__global__ void k_umem(float* __restrict__ outb, const float* __restrict__ keys) {
    int m = blockIdx.x, tid = threadIdx.x;
    __shared__ float red[256];
    float dninv = 1.0f / (g_denom[m] + 1e-8f);
    float a0 = g_qupd[(size_t)m * 512 + tid]       * dninv + keys[(size_t)m * 512 + tid];
    float a1 = g_qupd[(size_t)m * 512 + tid + 256] * dninv + keys[(size_t)m * 512 + tid + 256];
    float s = block_reduce_sum256(a0 * a0 + a1 * a1, red);
    float inv = 1.0f / fmaxf(sqrtf(s), 1e-12f);
    float* um = outb + UM_OFF + (size_t)m * 512;
    um[tid] = a0 * inv; um[tid + 256] = a1 * inv;
    if (m == 0 && tid == 0) {
        outb[LS_OFF]     = g_loss[0] * (1.0f / 16384.0f);
        outb[LS_OFF + 1] = g_loss[1] * (1.0f / 8388608.0f);
    }
}

// ---------------- launch ------------------------------------------------------
extern "C" void kernel_launch(void* const* d_in, const int* in_sizes, int n_in,
                              void* d_out, int out_size) {
    const float* q    = (const float*)d_in[0];
    const float* keys = (const float*)d_in[1];
    float* out = (float*)d_out;

    const int PREP_SM = 32 * 521 * 4;                     // 66688
    const int SM0 = 3 * (2 * AMATB + 2 * BMATB);          // 184320
    const int SM1 = 3 * (1 * AMATB + 1 * BMATB);          // 92160
    cudaFuncSetAttribute(k_prep,         cudaFuncAttributeMaxDynamicSharedMemorySize, PREP_SM);
    cudaFuncSetAttribute(k_mma<512, 0>,  cudaFuncAttributeMaxDynamicSharedMemorySize, SM0);
    cudaFuncSetAttribute(k_mma<2048, 1>, cudaFuncAttributeMaxDynamicSharedMemorySize, SM1);

    k_zero<<<1024, 256>>>();
    k_prep<<<dim3(32, 16), 256, PREP_SM>>>(q, out);
    k_keynorm<<<2000, 256>>>(keys);
    k_mma<512, 0><<<dim3(128, 8), 256, SM0>>>(out);       // 4th launch -> ncu capture slot
    k_colinv<<<8, 256>>>();
    k_rows2<<<16384, 256>>>(out, keys);
    k_keyT<<<dim3(64, 16), dim3(32, 8)>>>(keys);
    k_umem<<<2000, 256>>>(out, keys);
    k_mma<2048, 1><<<dim3(128, 2), 256, SM1>>>(out);
}

// round 14
// speedup vs baseline: 1.0516x; 1.0516x over previous
#include <cuda_runtime.h>
#include <cuda_bf16.h>
#include <math.h>
#include <stdint.h>

#define NN 16384
#define MM 2000
#define MP 2048

#define UQ_OFF 0LL
#define UM_OFF 16777216LL
#define SQ_OFF 17801216LL
#define SMO_OFF 50569216LL
#define LS_OFF 83337216LL
#define UQ_BSTRIDE 1048576LL

// ---------------- scratch ---------------------------------------------------
__device__ __align__(16) float g_qf[(size_t)NN*512];
__device__ __align__(16) __nv_bfloat16 g_qf_h[(size_t)NN*512], g_qf_l[(size_t)NN*512];
__device__ __align__(16) __nv_bfloat16 g_kn_h[(size_t)MP*512], g_kn_l[(size_t)MP*512];
__device__ __align__(16) __nv_bfloat16 g_kT_h[(size_t)512*MP];
__device__ __align__(16) __nv_bfloat16 g_sm_h[(size_t)NN*MP];
__device__ __align__(16) float g_colsum[MM];
__device__ float g_colmaxE[MM];
__device__ __align__(16) float g_colinv[MM];
__device__ float g_denom[MM];
__device__ __align__(16) float g_qupd[(size_t)MM*512];
__device__ float g_loss[2];

// ---------------- helpers ---------------------------------------------------
__device__ __forceinline__ bool gt2(float va, int ia, float vb, int ib) {
    return va > vb || (va == vb && (unsigned)ia < (unsigned)ib);
}
__device__ __forceinline__ float block_reduce_sum256(float v, float* red) {
    int tid = threadIdx.x;
    red[tid] = v; __syncthreads();
    #pragma unroll
    for (int s = 128; s > 0; s >>= 1) { if (tid < s) red[tid] += red[tid + s]; __syncthreads(); }
    float r = red[0]; __syncthreads(); return r;
}
__device__ __forceinline__ void split2(float v, __nv_bfloat16& h, __nv_bfloat16& l) {
    h = __float2bfloat16(v);
    l = __float2bfloat16(v - __bfloat162float(h));
}
__device__ __forceinline__ uint32_t s2u(const void* p) {
    uint32_t a;
    asm("{ .reg .u64 t; cvta.to.shared.u64 t, %1; cvt.u32.u64 %0, t; }" : "=r"(a) : "l"(p));
    return a;
}
__device__ __forceinline__ void ldm_x4(uint32_t* r, uint32_t addr) {
    asm volatile("ldmatrix.sync.aligned.m8n8.x4.shared.b16 {%0,%1,%2,%3}, [%4];"
        : "=r"(r[0]), "=r"(r[1]), "=r"(r[2]), "=r"(r[3]) : "r"(addr));
}
__device__ __forceinline__ void mma16816(float* c, const uint32_t* a, const uint32_t* b) {
    asm volatile("mma.sync.aligned.m16n8k16.row.col.f32.bf16.bf16.f32 "
        "{%0,%1,%2,%3}, {%4,%5,%6,%7}, {%8,%9}, {%0,%1,%2,%3};"
        : "+f"(c[0]), "+f"(c[1]), "+f"(c[2]), "+f"(c[3])
        : "r"(a[0]), "r"(a[1]), "r"(a[2]), "r"(a[3]), "r"(b[0]), "r"(b[1]));
}
#define CPA(dst, src) asm volatile("cp.async.cg.shared.global [%0], [%1], 16;" :: "r"(dst), "l"(src))
#define CPC()  asm volatile("cp.async.commit_group;" ::: "memory")

// ---------------- K0: zero scratch ------------------------------------------
__global__ void k_zero() {
    int i = blockIdx.x * 256 + threadIdx.x;       // grid 1024
    if (i < 256000) ((float4*)g_qupd)[i] = make_float4(0.f, 0.f, 0.f, 0.f);
    if (i < MM) { g_denom[i] = 0.f; g_colsum[i] = 0.f; g_colmaxE[i] = 0.f; }
    if (i < 2)  g_loss[i] = 0.f;
    if (i < 12288) {
        ((uint32_t*)(g_kn_h + (size_t)MM * 512))[i] = 0u;
        ((uint32_t*)(g_kn_l + (size_t)MM * 512))[i] = 0u;
    }
}

// ---------------- K1: fused query prep ---------------------------------------
__global__ __launch_bounds__(256) void k_prep(const float* __restrict__ q,
                                              float* __restrict__ outb) {
    extern __shared__ float sm[];                 // [32][521]
    __shared__ float inv_s[32];
    int hw0 = blockIdx.x * 32, b = blockIdx.y;
    int tid = threadIdx.x, lane = tid & 31, w = tid >> 5;
    const float* qb = q + (size_t)b * 524288;

    for (int d = w; d < 512; d += 8)
        sm[lane * 521 + d] = qb[(size_t)d * 1024 + hw0 + lane];
    __syncthreads();

    #pragma unroll
    for (int rr = 0; rr < 4; rr++) {
        int r = w * 4 + rr;
        float s = 0.f;
        #pragma unroll
        for (int k = 0; k < 16; k++) { float v = sm[r * 521 + lane + 32 * k]; s += v * v; }
        #pragma unroll
        for (int off = 16; off > 0; off >>= 1) s += __shfl_xor_sync(~0u, s, off);
        if (lane == 0) inv_s[r] = 1.0f / fmaxf(sqrtf(s), 1e-12f);
    }
    __syncthreads();

    float* uq = outb + (size_t)b * UQ_BSTRIDE;
    for (int d = w; d < 512; d += 8)
        uq[(size_t)d * 1024 + hw0 + lane] = sm[lane * 521 + d] * inv_s[lane];

    #pragma unroll
    for (int rr = 0; rr < 4; rr++) {
        int r = w * 4 + rr;
        float iv = inv_s[r];
        size_t nbase = (size_t)(b * 1024 + hw0 + r) * 512;
        #pragma unroll
        for (int k = 0; k < 16; k++) {
            int d = lane + 32 * k;
            float v = sm[r * 521 + d] * iv;
            __nv_bfloat16 h, lo; split2(v, h, lo);
            g_qf[nbase + d] = v; g_qf_h[nbase + d] = h; g_qf_l[nbase + d] = lo;
        }
    }
}

// ---------------- K2: normalized keys bf16 split -----------------------------
__global__ void k_keynorm(const float* __restrict__ keys) {
    int m = blockIdx.x, tid = threadIdx.x;
    __shared__ float red[256];
    const float* kp = keys + (size_t)m * 512;
    float v0 = kp[tid], v1 = kp[tid + 256];
    float s = block_reduce_sum256(v0 * v0 + v1 * v1, red);
    float inv = 1.0f / fmaxf(sqrtf(s), 1e-12f);
    __nv_bfloat16 h, lo;
    split2(v0 * inv, h, lo);
    g_kn_h[(size_t)m * 512 + tid] = h; g_kn_l[(size_t)m * 512 + tid] = lo;
    split2(v1 * inv, h, lo);
    g_kn_h[(size_t)m * 512 + tid + 256] = h; g_kn_l[(size_t)m * 512 + tid + 256] = lo;
}

// ---------------- K2b: raw keys^T bf16 hi ------------------------------------
__global__ void k_keyT(const float* __restrict__ keys) {
    int m0 = blockIdx.x * 32, d0 = blockIdx.y * 32;
    int tx = threadIdx.x, ty = threadIdx.y;
    __shared__ float t[32][33];
    #pragma unroll
    for (int qq = 0; qq < 4; qq++) {
        int ml = ty + qq * 8, m = m0 + ml;
        t[ml][tx] = (m < MM) ? keys[(size_t)m * 512 + d0 + tx] : 0.f;
    }
    __syncthreads();
    #pragma unroll
    for (int qq = 0; qq < 4; qq++) {
        int dl = ty + qq * 8;
        g_kT_h[(size_t)(d0 + dl) * MP + m0 + tx] = __float2bfloat16(t[tx][dl]);
    }
}

// ---------------- HMMA GEMM: 128x128 tile, warp 64x32, <=128 regs ------------
// MODE 0: E=exp(10*(qf@kn^T)) -> SQ + col sum/max   (3 products)
// MODE 1: SM@keysT -> updated_query 2nd half         (1 product)
#define ROWB 80
#define MATB 10240

template<int KTOT, int MODE>
__global__ __launch_bounds__(256, 2) void k_mma(float* __restrict__ outb) {
    constexpr int NA   = (MODE == 0) ? 2 : 1;
    constexpr int NB   = (MODE == 0) ? 2 : 1;
    constexpr int NMATS = NA + NB;
    constexpr int AOFF = NA * MATB;
    constexpr int STGB = NMATS * MATB;
    extern __shared__ char smc[];
    const uint32_t smb = s2u(smc);
    const int tid = threadIdx.x;
    const int lane = tid & 31, wid = tid >> 5;
    const int wr = wid & 1, wc = wid >> 1;        // wr 0-1 (M64), wc 0-3 (N32)
    const int i0 = blockIdx.x * 128, j0 = blockIdx.y * 128;

    const __nv_bfloat16* Ah = (MODE == 0) ? g_qf_h : g_sm_h;
    const __nv_bfloat16* Al = (MODE == 0) ? g_qf_l : g_sm_h;
    const __nv_bfloat16* Bh = (MODE == 0) ? g_kn_h : g_kT_h;
    const __nv_bfloat16* Bl = (MODE == 0) ? g_kn_l : g_kT_h;
    const int lda = (MODE == 0) ? 512 : MP;
    const int ldb = (MODE == 0) ? 512 : MP;

    float c[4][4][4];                             // 64 accumulators
    #pragma unroll
    for (int a = 0; a < 4; a++)
        #pragma unroll
        for (int b = 0; b < 4; b++)
            #pragma unroll
            for (int d = 0; d < 4; d++) c[a][b][d] = 0.f;

    const int NS = KTOT / 32;

    auto issue = [&](int stg, uint32_t dst0) {
        size_t k0 = (size_t)stg * 32;
        // all mats are 128 rows x 80B; order [Ah, Al, Bh, Bl] (MODE0) / [Ah, Bh]
        #pragma unroll
        for (int i = 0; i < NMATS * 2; i++) {
            int chunk = tid + 256 * i;
            int mat = chunk >> 9, row = (chunk >> 2) & 127, kc = chunk & 3;
            const __nv_bfloat16* p;
            int rb, gl;
            if (MODE == 0) {
                p = (mat == 0) ? Ah : (mat == 1) ? Al : (mat == 2) ? Bh : Bl;
                rb = (mat < 2) ? i0 : j0; gl = (mat < 2) ? lda : ldb;
            } else {
                p = (mat == 0) ? Ah : Bh;
                rb = (mat == 0) ? i0 : j0; gl = (mat == 0) ? lda : ldb;
            }
            CPA(dst0 + mat * MATB + row * ROWB + kc * 16, p + (size_t)(rb + row) * gl + k0 + kc * 8);
        }
        CPC();
    };

    issue(0, smb);

    for (int s = 0; s < NS; s++) {
        if (s + 1 < NS) {
            issue(s + 1, smb + ((s + 1) & 1) * STGB);
            asm volatile("cp.async.wait_group 1;" ::: "memory");
        } else {
            asm volatile("cp.async.wait_group 0;" ::: "memory");
        }
        __syncthreads();

        uint32_t sb = smb + (s & 1) * STGB;
        #pragma unroll
        for (int kh = 0; kh < 2; kh++) {
            const int k16 = kh * 16;
            uint32_t afh[4][4], afl[4][4], bfh[2][4], bfl[2][4];
            #pragma unroll
            for (int mt = 0; mt < 4; mt++) {
                uint32_t ad = sb + (uint32_t)(wr * 64 + mt * 16 + (lane & 15)) * ROWB
                            + (uint32_t)(k16 + ((lane >> 4) << 3)) * 2;
                ldm_x4(afh[mt], ad);
                if (MODE == 0) ldm_x4(afl[mt], ad + MATB);
            }
            #pragma unroll
            for (int np = 0; np < 2; np++) {
                int n = wc * 32 + np * 16 + ((lane >> 4) << 3) + (lane & 7);
                int kk = k16 + (((lane >> 3) & 1) << 3);
                uint32_t bd = sb + AOFF + (uint32_t)n * ROWB + (uint32_t)kk * 2;
                ldm_x4(bfh[np], bd);
                if (MODE == 0) ldm_x4(bfl[np], bd + MATB);
            }
            #pragma unroll
            for (int mt = 0; mt < 4; mt++)
                #pragma unroll
                for (int np = 0; np < 2; np++) {
                    mma16816(c[mt][np * 2],     afh[mt], &bfh[np][0]);
                    mma16816(c[mt][np * 2 + 1], afh[mt], &bfh[np][2]);
                    if (MODE == 0) {
                        mma16816(c[mt][np * 2],     afl[mt], &bfh[np][0]);
                        mma16816(c[mt][np * 2 + 1], afl[mt], &bfh[np][2]);
                        mma16816(c[mt][np * 2],     afh[mt], &bfl[np][0]);
                        mma16816(c[mt][np * 2 + 1], afh[mt], &bfl[np][2]);
                    }
                }
        }
        __syncthreads();
    }

    // ---------------- epilogue ----------------
    const int rbase = i0 + wr * 64 + (lane >> 2);
    const int cbase = j0 + wc * 32 + (lane & 3) * 2;
    if (MODE == 0) {
        float csum[4][2], cmax[4][2];
        #pragma unroll
        for (int nt = 0; nt < 4; nt++) { csum[nt][0] = csum[nt][1] = 0.f; cmax[nt][0] = cmax[nt][1] = 0.f; }
        #pragma unroll
        for (int mt = 0; mt < 4; mt++) {
            #pragma unroll
            for (int h2 = 0; h2 < 2; h2++) {
                int r = rbase + mt * 16 + h2 * 8;
                float* Erow = outb + SQ_OFF + (size_t)r * MM;
                #pragma unroll
                for (int nt = 0; nt < 4; nt++) {
                    int cc = cbase + nt * 8;
                    float2 e;
                    e.x = __expf(10.f * c[mt][nt][h2 * 2]);
                    e.y = __expf(10.f * c[mt][nt][h2 * 2 + 1]);
                    if (cc < MM) *(float2*)(Erow + cc) = e;
                    csum[nt][0] += e.x; csum[nt][1] += e.y;
                    cmax[nt][0] = fmaxf(cmax[nt][0], e.x);
                    cmax[nt][1] = fmaxf(cmax[nt][1], e.y);
                }
            }
        }
        #pragma unroll
        for (int off = 4; off < 32; off <<= 1) {
            #pragma unroll
            for (int nt = 0; nt < 4; nt++) {
                csum[nt][0] += __shfl_xor_sync(~0u, csum[nt][0], off);
                csum[nt][1] += __shfl_xor_sync(~0u, csum[nt][1], off);
                cmax[nt][0] = fmaxf(cmax[nt][0], __shfl_xor_sync(~0u, cmax[nt][0], off));
                cmax[nt][1] = fmaxf(cmax[nt][1], __shfl_xor_sync(~0u, cmax[nt][1], off));
            }
        }
        if ((lane >> 2) == 0) {
            #pragma unroll
            for (int nt = 0; nt < 4; nt++) {
                int col = cbase + nt * 8;
                if (col < MM) {
                    atomicAdd(&g_colsum[col], csum[nt][0]);
                    atomicMax((int*)&g_colmaxE[col], __float_as_int(cmax[nt][0]));
                    atomicAdd(&g_colsum[col + 1], csum[nt][1]);
                    atomicMax((int*)&g_colmaxE[col + 1], __float_as_int(cmax[nt][1]));
                }
            }
        }
    } else {
        #pragma unroll
        for (int mt = 0; mt < 4; mt++) {
            #pragma unroll
            for (int h2 = 0; h2 < 2; h2++) {
                int r = rbase + mt * 16 + h2 * 8;
                int bq = r >> 10, hw = r & 1023;
                float* base = outb + ((size_t)bq * 1024 + 512) * 1024 + hw;
                #pragma unroll
                for (int nt = 0; nt < 4; nt++) {
                    int cc = cbase + nt * 8;
                    base[(size_t)cc * 1024]       = c[mt][nt][h2 * 2];
                    base[(size_t)(cc + 1) * 1024] = c[mt][nt][h2 * 2 + 1];
                }
            }
        }
    }
}

__global__ void k_colinv() {
    int m = blockIdx.x * 256 + threadIdx.x;
    if (m < MM) g_colinv[m] = 1.0f / g_colsum[m];
}

// ---------------- K5: fused row pass (+ segment accumulate) ------------------
__global__ __launch_bounds__(256) void k_rows2(float* __restrict__ outb,
                                               const float* __restrict__ keys) {
    int n = blockIdx.x, tid = threadIdx.x, lane = tid & 31, w = tid >> 5;
    float* Er = outb + SQ_OFF  + (size_t)n * MM;
    float* Sr = outb + SMO_OFF + (size_t)n * MM;
    __shared__ float row[2000];
    __shared__ float sv1[8], sv2[8];
    __shared__ int   si1[8], si2[8];
    __shared__ float red[4][8];
    __shared__ float s_zs, s_wr;
    __shared__ int   s_g1, s_g2;

    float v1 = -3.0e38f, v2 = -3.0e38f; int i1 = 0x7FFFFFFF, i2 = 0x7FFFFFFF;
    float zs = 0.f;
    for (int m4 = tid; m4 < 500; m4 += 256) {
        float4 v = ((const float4*)Er)[m4];
        ((float4*)row)[m4] = v;
        zs += (v.x + v.y) + (v.z + v.w);
        float a[4] = {v.x, v.y, v.z, v.w};
        #pragma unroll
        for (int j = 0; j < 4; j++) {
            int m = m4 * 4 + j; float vv = a[j];
            if (gt2(vv, m, v1, i1)) { v2 = v1; i2 = i1; v1 = vv; i1 = m; }
            else if (gt2(vv, m, v2, i2)) { v2 = vv; i2 = m; }
        }
    }
    #pragma unroll
    for (int off = 16; off > 0; off >>= 1) {
        float w1 = __shfl_down_sync(~0u, v1, off); int j1 = __shfl_down_sync(~0u, i1, off);
        float w2 = __shfl_down_sync(~0u, v2, off); int j2 = __shfl_down_sync(~0u, i2, off);
        zs += __shfl_down_sync(~0u, zs, off);
        if (gt2(w1, j1, v1, i1)) {
            float o2; int p2;
            if (gt2(v1, i1, w2, j2)) { o2 = v1; p2 = i1; } else { o2 = w2; p2 = j2; }
            v1 = w1; i1 = j1; v2 = o2; i2 = p2;
        } else if (gt2(w1, j1, v2, i2)) { v2 = w1; i2 = j1; }
    }
    if (lane == 0) { sv1[w] = v1; si1[w] = i1; sv2[w] = v2; si2[w] = i2; red[0][w] = zs; }
    __syncthreads();
    if (tid == 0) {
        float b1 = sv1[0], b2 = sv2[0]; int c1 = si1[0], c2i = si2[0];
        #pragma unroll
        for (int k = 1; k < 8; k++) {
            float w1 = sv1[k], w2 = sv2[k]; int j1 = si1[k], j2 = si2[k];
            if (gt2(w1, j1, b1, c1)) {
                if (gt2(b1, c1, w2, j2)) { b2 = b1; c2i = c1; } else { b2 = w2; c2i = j2; }
                b1 = w1; c1 = j1;
            } else if (gt2(w1, j1, b2, c2i)) { b2 = w1; c2i = j1; }
        }
        s_g1 = c1; s_g2 = c2i;
        s_zs = ((red[0][0] + red[0][1]) + (red[0][2] + red[0][3]))
             + ((red[0][4] + red[0][5]) + (red[0][6] + red[0][7]));
        float ci = g_colinv[c1];
        float wr = (b1 * ci) / (g_colmaxE[c1] * ci + 1e-8f);
        s_wr = wr;
        atomicAdd(&g_denom[c1], wr);
    }
    __syncthreads();
    int gg1 = s_g1, gg2 = s_g2;
    float invZ = 1.0f / s_zs;
    float wr = s_wr;

    __nv_bfloat162* smh2 = (__nv_bfloat162*)(g_sm_h + (size_t)n * MP);
    for (int m4 = tid; m4 < 500; m4 += 256) {
        float4 e = ((const float4*)row)[m4];
        float4 sm4 = make_float4(e.x * invZ, e.y * invZ, e.z * invZ, e.w * invZ);
        ((float4*)Sr)[m4] = sm4;
        float4 ci = ((const float4*)g_colinv)[m4];
        ((float4*)Er)[m4] = make_float4(e.x * ci.x, e.y * ci.y, e.z * ci.z, e.w * ci.w);
        smh2[m4 * 2]     = __floats2bfloat162_rn(sm4.x, sm4.y);
        smh2[m4 * 2 + 1] = __floats2bfloat162_rn(sm4.z, sm4.w);
    }
    if (tid < 24) smh2[1000 + tid] = __floats2bfloat162_rn(0.f, 0.f);

    float c2 = 0.f, p2s = 0.f, n2s = 0.f;
    const float* qrow = g_qf + (size_t)n * 512;
    const float* k1 = keys + (size_t)gg1 * 512;
    const float* k2 = keys + (size_t)gg2 * 512;
    float* dst = g_qupd + (size_t)gg1 * 512;
    for (int d = tid; d < 512; d += 256) {
        float qv = qrow[d];
        float df = qv - k1[d];           c2 += df * df;
        float dp = df + 1e-6f;           p2s += dp * dp;
        float dn = (qv - k2[d]) + 1e-6f; n2s += dn * dn;
        atomicAdd(&dst[d], wr * qv);
    }
    #pragma unroll
    for (int off = 16; off > 0; off >>= 1) {
        c2  += __shfl_down_sync(~0u, c2,  off);
        p2s += __shfl_down_sync(~0u, p2s, off);
        n2s += __shfl_down_sync(~0u, n2s, off);
    }
    if (lane == 0) { red[1][w] = c2; red[2][w] = p2s; red[3][w] = n2s; }
    __syncthreads();
    if (tid == 0) {
        c2 = p2s = n2s = 0.f;
        #pragma unroll
        for (int k = 0; k < 8; k++) { c2 += red[1][k]; p2s += red[2][k]; n2s += red[3][k]; }
        atomicAdd(&g_loss[0], fmaxf(sqrtf(p2s) - sqrtf(n2s) + 1.0f, 0.0f));
        atomicAdd(&g_loss[1], c2);
    }
}

// ---------------- K8: updated_memory (+ finalize losses) ---------------------
__global__ void k_umem(float* __restrict__ outb, const float* __restrict__ keys) {
    int m = blockIdx.x, tid = threadIdx.x;
    __shared__ float red[256];
    float dninv = 1.0f / (g_denom[m] + 1e-8f);
    float a0 = g_qupd[(size_t)m * 512 + tid]       * dninv + keys[(size_t)m * 512 + tid];
    float a1 = g_qupd[(size_t)m * 512 + tid + 256] * dninv + keys[(size_t)m * 512 + tid + 256];
    float s = block_reduce_sum256(a0 * a0 + a1 * a1, red);
    float inv = 1.0f / fmaxf(sqrtf(s), 1e-12f);
    float* um = outb + UM_OFF + (size_t)m * 512;
    um[tid] = a0 * inv; um[tid + 256] = a1 * inv;
    if (m == 0 && tid == 0) {
        outb[LS_OFF]     = g_loss[0] * (1.0f / 16384.0f);
        outb[LS_OFF + 1] = g_loss[1] * (1.0f / 8388608.0f);
    }
}

// ---------------- launch ------------------------------------------------------
extern "C" void kernel_launch(void* const* d_in, const int* in_sizes, int n_in,
                              void* d_out, int out_size) {
    const float* q    = (const float*)d_in[0];
    const float* keys = (const float*)d_in[1];
    float* out = (float*)d_out;

    const int PREP_SM = 32 * 521 * 4;             // 66688
    const int SM0 = 2 * 4 * MATB;                 // 81920 (2 stages x 4 mats)
    const int SM1 = 2 * 2 * MATB;                 // 40960
    cudaFuncSetAttribute(k_prep,         cudaFuncAttributeMaxDynamicSharedMemorySize, PREP_SM);
    cudaFuncSetAttribute(k_mma<512, 0>,  cudaFuncAttributeMaxDynamicSharedMemorySize, SM0);
    cudaFuncSetAttribute(k_mma<2048, 1>, cudaFuncAttributeMaxDynamicSharedMemorySize, SM1);

    k_zero<<<1024, 256>>>();
    k_prep<<<dim3(32, 16), 256, PREP_SM>>>(q, out);
    k_keynorm<<<2000, 256>>>(keys);
    k_mma<512, 0><<<dim3(128, 16), 256, SM0>>>(out);      // 4th launch -> ncu capture slot
    k_colinv<<<8, 256>>>();
    k_rows2<<<16384, 256>>>(out, keys);
    k_keyT<<<dim3(64, 16), dim3(32, 8)>>>(keys);
    k_umem<<<2000, 256>>>(out, keys);
    k_mma<2048, 1><<<dim3(128, 4), 256, SM1>>>(out);
}

// round 17
// speedup vs baseline: 1.0856x; 1.0324x over previous
#include <cuda_runtime.h>
#include <cuda_fp16.h>
#include <math.h>
#include <stdint.h>

#define NN 16384
#define MM 2000
#define MP 2048

#define UQ_OFF 0LL
#define UM_OFF 16777216LL
#define SQ_OFF 17801216LL
#define SMO_OFF 50569216LL
#define LS_OFF 83337216LL
#define UQ_BSTRIDE 1048576LL

// ---------------- scratch ---------------------------------------------------
__device__ __align__(16) float g_qf[(size_t)NN*512];
__device__ __align__(16) __half g_qf_h[(size_t)NN*512], g_qf_l[(size_t)NN*512];
__device__ __align__(16) __half g_kn_h[(size_t)MP*512];
__device__ __align__(16) __half g_kT_h[(size_t)512*MP];
__device__ __align__(16) __half g_sm_h[(size_t)NN*MP];
__device__ __align__(16) float g_colsum[MM];
__device__ float g_colmaxE[MM];
__device__ __align__(16) float g_colinv[MM];
__device__ float g_kninv[MM];
__device__ float g_denom[MM];
__device__ __align__(16) float g_qupd[(size_t)MM*512];
__device__ float g_loss[2];

// ---------------- helpers ---------------------------------------------------
__device__ __forceinline__ bool gt2(float va, int ia, float vb, int ib) {
    return va > vb || (va == vb && (unsigned)ia < (unsigned)ib);
}
__device__ __forceinline__ float block_reduce_sum256(float v, float* red) {
    int tid = threadIdx.x;
    red[tid] = v; __syncthreads();
    #pragma unroll
    for (int s = 128; s > 0; s >>= 1) { if (tid < s) red[tid] += red[tid + s]; __syncthreads(); }
    float r = red[0]; __syncthreads(); return r;
}
__device__ __forceinline__ void split2h(float v, __half& h, __half& l) {
    h = __float2half_rn(v);
    l = __float2half_rn(v - __half2float(h));
}
__device__ __forceinline__ uint32_t s2u(const void* p) {
    uint32_t a;
    asm("{ .reg .u64 t; cvta.to.shared.u64 t, %1; cvt.u32.u64 %0, t; }" : "=r"(a) : "l"(p));
    return a;
}
__device__ __forceinline__ void ldm_x4(uint32_t* r, uint32_t addr) {
    asm volatile("ldmatrix.sync.aligned.m8n8.x4.shared.b16 {%0,%1,%2,%3}, [%4];"
        : "=r"(r[0]), "=r"(r[1]), "=r"(r[2]), "=r"(r[3]) : "r"(addr));
}
__device__ __forceinline__ void mma16816(float* c, const uint32_t* a, const uint32_t* b) {
    asm volatile("mma.sync.aligned.m16n8k16.row.col.f32.f16.f16.f32 "
        "{%0,%1,%2,%3}, {%4,%5,%6,%7}, {%8,%9}, {%0,%1,%2,%3};"
        : "+f"(c[0]), "+f"(c[1]), "+f"(c[2]), "+f"(c[3])
        : "r"(a[0]), "r"(a[1]), "r"(a[2]), "r"(a[3]), "r"(b[0]), "r"(b[1]));
}
#define CPA(dst, src) asm volatile("cp.async.cg.shared.global [%0], [%1], 16;" :: "r"(dst), "l"(src))
#define CPC()  asm volatile("cp.async.commit_group;" ::: "memory")

// ---------------- K0: zero scratch ------------------------------------------
__global__ void k_zero() {
    int i = blockIdx.x * 256 + threadIdx.x;       // grid 1024
    if (i < 256000) ((float4*)g_qupd)[i] = make_float4(0.f, 0.f, 0.f, 0.f);
    if (i < MM) { g_denom[i] = 0.f; g_colsum[i] = 0.f; g_colmaxE[i] = 0.f; }
    if (i < 2)  g_loss[i] = 0.f;
    if (i < 24576)                                // zero 48 padded key rows (fp16)
        ((uint16_t*)(g_kn_h + (size_t)MM * 512))[i] = 0u;
}

// ---------------- K1: fused query prep ---------------------------------------
__global__ __launch_bounds__(256) void k_prep(const float* __restrict__ q,
                                              float* __restrict__ outb) {
    extern __shared__ float sm[];                 // [32][521]
    __shared__ float inv_s[32];
    int hw0 = blockIdx.x * 32, b = blockIdx.y;
    int tid = threadIdx.x, lane = tid & 31, w = tid >> 5;
    const float* qb = q + (size_t)b * 524288;

    for (int d = w; d < 512; d += 8)
        sm[lane * 521 + d] = qb[(size_t)d * 1024 + hw0 + lane];
    __syncthreads();

    #pragma unroll
    for (int rr = 0; rr < 4; rr++) {
        int r = w * 4 + rr;
        float s = 0.f;
        #pragma unroll
        for (int k = 0; k < 16; k++) { float v = sm[r * 521 + lane + 32 * k]; s += v * v; }
        #pragma unroll
        for (int off = 16; off > 0; off >>= 1) s += __shfl_xor_sync(~0u, s, off);
        if (lane == 0) inv_s[r] = 1.0f / fmaxf(sqrtf(s), 1e-12f);
    }
    __syncthreads();

    float* uq = outb + (size_t)b * UQ_BSTRIDE;
    for (int d = w; d < 512; d += 8)
        uq[(size_t)d * 1024 + hw0 + lane] = sm[lane * 521 + d] * inv_s[lane];

    #pragma unroll
    for (int rr = 0; rr < 4; rr++) {
        int r = w * 4 + rr;
        float iv = inv_s[r];
        size_t nbase = (size_t)(b * 1024 + hw0 + r) * 512;
        #pragma unroll
        for (int k = 0; k < 16; k++) {
            int d = lane + 32 * k;
            float v = sm[r * 521 + d] * iv;
            __half h, lo; split2h(v, h, lo);
            g_qf[nbase + d] = v; g_qf_h[nbase + d] = h; g_qf_l[nbase + d] = lo;
        }
    }
}

// ---------------- K2: normalized keys fp16 + inv norms -----------------------
__global__ void k_keynorm(const float* __restrict__ keys) {
    int m = blockIdx.x, tid = threadIdx.x;
    __shared__ float red[256];
    const float* kp = keys + (size_t)m * 512;
    float v0 = kp[tid], v1 = kp[tid + 256];
    float s = block_reduce_sum256(v0 * v0 + v1 * v1, red);
    float inv = 1.0f / fmaxf(sqrtf(s), 1e-12f);
    g_kn_h[(size_t)m * 512 + tid]       = __float2half_rn(v0 * inv);
    g_kn_h[(size_t)m * 512 + tid + 256] = __float2half_rn(v1 * inv);
    if (tid == 0) g_kninv[m] = inv;
}

// ---------------- K2b: raw keys^T fp16 ---------------------------------------
__global__ void k_keyT(const float* __restrict__ keys) {
    int m0 = blockIdx.x * 32, d0 = blockIdx.y * 32;
    int tx = threadIdx.x, ty = threadIdx.y;
    __shared__ float t[32][33];
    #pragma unroll
    for (int qq = 0; qq < 4; qq++) {
        int ml = ty + qq * 8, m = m0 + ml;
        t[ml][tx] = (m < MM) ? keys[(size_t)m * 512 + d0 + tx] : 0.f;
    }
    __syncthreads();
    #pragma unroll
    for (int qq = 0; qq < 4; qq++) {
        int dl = ty + qq * 8;
        g_kT_h[(size_t)(d0 + dl) * MP + m0 + tx] = __float2half_rn(t[tx][dl]);
    }
}

// ---------------- HMMA GEMM: fp16, 128x128 tile, warp 64x32 ------------------
// MODE 0: E=exp(10*(qf@kn^T)) -> SQ + col sum/max   (Ah*B + Al*B)
// MODE 1: SM@keysT -> updated_query 2nd half         (1 product)
#define ROWB 80
#define MATB 10240

template<int KTOT, int MODE>
__global__ __launch_bounds__(256, 2) void k_mma(float* __restrict__ outb) {
    constexpr int NA   = (MODE == 0) ? 2 : 1;
    constexpr int NMATS = NA + 1;
    constexpr int AOFF = NA * MATB;
    constexpr int STGB = NMATS * MATB;
    extern __shared__ char smc[];
    const uint32_t smb = s2u(smc);
    const int tid = threadIdx.x;
    const int lane = tid & 31, wid = tid >> 5;
    const int wr = wid & 1, wc = wid >> 1;        // wr 0-1 (M64), wc 0-3 (N32)
    const int i0 = blockIdx.x * 128, j0 = blockIdx.y * 128;

    const __half* Ah = (MODE == 0) ? g_qf_h : g_sm_h;
    const __half* Al = (MODE == 0) ? g_qf_l : g_sm_h;   // unused MODE 1
    const __half* Bh = (MODE == 0) ? g_kn_h : g_kT_h;
    const int lda = (MODE == 0) ? 512 : MP;
    const int ldb = (MODE == 0) ? 512 : MP;

    float c[4][4][4];                             // 64 accumulators
    #pragma unroll
    for (int a = 0; a < 4; a++)
        #pragma unroll
        for (int b = 0; b < 4; b++)
            #pragma unroll
            for (int d = 0; d < 4; d++) c[a][b][d] = 0.f;

    const int NS = KTOT / 32;

    auto issue = [&](int stg, uint32_t dst0) {
        size_t k0 = (size_t)stg * 32;
        #pragma unroll
        for (int i = 0; i < NMATS * 2; i++) {
            int chunk = tid + 256 * i;
            int mat = chunk >> 9, row = (chunk >> 2) & 127, kc = chunk & 3;
            const __half* p;
            int rb, gl;
            if (MODE == 0) {
                p = (mat == 0) ? Ah : (mat == 1) ? Al : Bh;
                rb = (mat < 2) ? i0 : j0; gl = (mat < 2) ? lda : ldb;
            } else {
                p = (mat == 0) ? Ah : Bh;
                rb = (mat == 0) ? i0 : j0; gl = (mat == 0) ? lda : ldb;
            }
            CPA(dst0 + mat * MATB + row * ROWB + kc * 16, p + (size_t)(rb + row) * gl + k0 + kc * 8);
        }
        CPC();
    };

    issue(0, smb);

    for (int s = 0; s < NS; s++) {
        if (s + 1 < NS) {
            issue(s + 1, smb + ((s + 1) & 1) * STGB);
            asm volatile("cp.async.wait_group 1;" ::: "memory");
        } else {
            asm volatile("cp.async.wait_group 0;" ::: "memory");
        }
        __syncthreads();

        uint32_t sb = smb + (s & 1) * STGB;
        #pragma unroll
        for (int kh = 0; kh < 2; kh++) {
            const int k16 = kh * 16;
            uint32_t afh[4][4], afl[4][4], bfh[2][4];
            #pragma unroll
            for (int mt = 0; mt < 4; mt++) {
                uint32_t ad = sb + (uint32_t)(wr * 64 + mt * 16 + (lane & 15)) * ROWB
                            + (uint32_t)(k16 + ((lane >> 4) << 3)) * 2;
                ldm_x4(afh[mt], ad);
                if (MODE == 0) ldm_x4(afl[mt], ad + MATB);
            }
            #pragma unroll
            for (int np = 0; np < 2; np++) {
                int n = wc * 32 + np * 16 + ((lane >> 4) << 3) + (lane & 7);
                int kk = k16 + (((lane >> 3) & 1) << 3);
                uint32_t bd = sb + AOFF + (uint32_t)n * ROWB + (uint32_t)kk * 2;
                ldm_x4(bfh[np], bd);
            }
            #pragma unroll
            for (int mt = 0; mt < 4; mt++)
                #pragma unroll
                for (int np = 0; np < 2; np++) {
                    mma16816(c[mt][np * 2],     afh[mt], &bfh[np][0]);
                    mma16816(c[mt][np * 2 + 1], afh[mt], &bfh[np][2]);
                    if (MODE == 0) {
                        mma16816(c[mt][np * 2],     afl[mt], &bfh[np][0]);
                        mma16816(c[mt][np * 2 + 1], afl[mt], &bfh[np][2]);
                    }
                }
        }
        __syncthreads();
    }

    // ---------------- epilogue ----------------
    const int rbase = i0 + wr * 64 + (lane >> 2);
    const int cbase = j0 + wc * 32 + (lane & 3) * 2;
    if (MODE == 0) {
        float csum[4][2], cmax[4][2];
        #pragma unroll
        for (int nt = 0; nt < 4; nt++) { csum[nt][0] = csum[nt][1] = 0.f; cmax[nt][0] = cmax[nt][1] = 0.f; }
        #pragma unroll
        for (int mt = 0; mt < 4; mt++) {
            #pragma unroll
            for (int h2 = 0; h2 < 2; h2++) {
                int r = rbase + mt * 16 + h2 * 8;
                float* Erow = outb + SQ_OFF + (size_t)r * MM;
                #pragma unroll
                for (int nt = 0; nt < 4; nt++) {
                    int cc = cbase + nt * 8;
                    float2 e;
                    e.x = __expf(10.f * c[mt][nt][h2 * 2]);
                    e.y = __expf(10.f * c[mt][nt][h2 * 2 + 1]);
                    if (cc < MM) *(float2*)(Erow + cc) = e;
                    csum[nt][0] += e.x; csum[nt][1] += e.y;
                    cmax[nt][0] = fmaxf(cmax[nt][0], e.x);
                    cmax[nt][1] = fmaxf(cmax[nt][1], e.y);
                }
            }
        }
        #pragma unroll
        for (int off = 4; off < 32; off <<= 1) {
            #pragma unroll
            for (int nt = 0; nt < 4; nt++) {
                csum[nt][0] += __shfl_xor_sync(~0u, csum[nt][0], off);
                csum[nt][1] += __shfl_xor_sync(~0u, csum[nt][1], off);
                cmax[nt][0] = fmaxf(cmax[nt][0], __shfl_xor_sync(~0u, cmax[nt][0], off));
                cmax[nt][1] = fmaxf(cmax[nt][1], __shfl_xor_sync(~0u, cmax[nt][1], off));
            }
        }
        if ((lane >> 2) == 0) {
            #pragma unroll
            for (int nt = 0; nt < 4; nt++) {
                int col = cbase + nt * 8;
                if (col < MM) {
                    atomicAdd(&g_colsum[col], csum[nt][0]);
                    atomicMax((int*)&g_colmaxE[col], __float_as_int(cmax[nt][0]));
                    atomicAdd(&g_colsum[col + 1], csum[nt][1]);
                    atomicMax((int*)&g_colmaxE[col + 1], __float_as_int(cmax[nt][1]));
                }
            }
        }
    } else {
        #pragma unroll
        for (int mt = 0; mt < 4; mt++) {
            #pragma unroll
            for (int h2 = 0; h2 < 2; h2++) {
                int r = rbase + mt * 16 + h2 * 8;
                int bq = r >> 10, hw = r & 1023;
                float* base = outb + ((size_t)bq * 1024 + 512) * 1024 + hw;
                #pragma unroll
                for (int nt = 0; nt < 4; nt++) {
                    int cc = cbase + nt * 8;
                    base[(size_t)cc * 1024]       = c[mt][nt][h2 * 2];
                    base[(size_t)(cc + 1) * 1024] = c[mt][nt][h2 * 2 + 1];
                }
            }
        }
    }
}

__global__ void k_colinv() {
    int m = blockIdx.x * 256 + threadIdx.x;
    if (m < MM) g_colinv[m] = 1.0f / g_colsum[m];
}

// ---------------- K5: fused row pass + exact top-2 refinement ----------------
__global__ __launch_bounds__(256) void k_rows2(float* __restrict__ outb,
                                               const float* __restrict__ keys) {
    int n = blockIdx.x, tid = threadIdx.x, lane = tid & 31, w = tid >> 5;
    float* Er = outb + SQ_OFF  + (size_t)n * MM;
    float* Sr = outb + SMO_OFF + (size_t)n * MM;
    const float* qrow = g_qf + (size_t)n * 512;
    __shared__ float row[2000];
    __shared__ float sv1[8], sv2[8];
    __shared__ int   si1[8], si2[8];
    __shared__ float red[4][8];
    __shared__ float s_ex[16];
    __shared__ int   s_idx[16];
    __shared__ float s_zs, s_wr;
    __shared__ int   s_g1, s_g2;

    float v1 = -3.0e38f, v2 = -3.0e38f; int i1 = 0x7FFFFFFF, i2 = 0x7FFFFFFF;
    float zs = 0.f;
    for (int m4 = tid; m4 < 500; m4 += 256) {
        float4 v = ((const float4*)Er)[m4];
        ((float4*)row)[m4] = v;
        zs += (v.x + v.y) + (v.z + v.w);
        float a[4] = {v.x, v.y, v.z, v.w};
        #pragma unroll
        for (int j = 0; j < 4; j++) {
            int m = m4 * 4 + j; float vv = a[j];
            if (gt2(vv, m, v1, i1)) { v2 = v1; i2 = i1; v1 = vv; i1 = m; }
            else if (gt2(vv, m, v2, i2)) { v2 = vv; i2 = m; }
        }
    }
    #pragma unroll
    for (int off = 16; off > 0; off >>= 1) {
        float w1 = __shfl_down_sync(~0u, v1, off); int j1 = __shfl_down_sync(~0u, i1, off);
        float w2 = __shfl_down_sync(~0u, v2, off); int j2 = __shfl_down_sync(~0u, i2, off);
        zs += __shfl_down_sync(~0u, zs, off);
        if (gt2(w1, j1, v1, i1)) {
            float o2; int p2;
            if (gt2(v1, i1, w2, j2)) { o2 = v1; p2 = i1; } else { o2 = w2; p2 = j2; }
            v1 = w1; i1 = j1; v2 = o2; i2 = p2;
        } else if (gt2(w1, j1, v2, i2)) { v2 = w1; i2 = j1; }
    }
    if (lane == 0) { sv1[w] = v1; si1[w] = i1; sv2[w] = v2; si2[w] = i2; red[0][w] = zs; }
    __syncthreads();

    // exact fp32 re-score of the 16 warp-level candidates (warp w -> cands w, w+8)
    #pragma unroll
    for (int cc = 0; cc < 2; cc++) {
        int c = w + cc * 8;
        int idx = (c < 8) ? si1[c] : si2[c - 8];
        const float* kr = keys + (size_t)idx * 512;
        float dt = 0.f;
        #pragma unroll 4
        for (int d = lane; d < 512; d += 32) dt += qrow[d] * kr[d];
        #pragma unroll
        for (int off = 16; off > 0; off >>= 1) dt += __shfl_xor_sync(~0u, dt, off);
        if (lane == 0) { s_ex[c] = dt * g_kninv[idx]; s_idx[c] = idx; }
    }
    __syncthreads();
    if (tid == 0) {
        float b1 = -3.0e38f, b2 = -3.0e38f; int c1 = 0x7FFFFFFF, c2i = 0x7FFFFFFF;
        #pragma unroll
        for (int k = 0; k < 16; k++) {
            float vv = s_ex[k]; int ii = s_idx[k];
            if (gt2(vv, ii, b1, c1)) { b2 = b1; c2i = c1; b1 = vv; c1 = ii; }
            else if (gt2(vv, ii, b2, c2i)) { b2 = vv; c2i = ii; }
        }
        s_g1 = c1; s_g2 = c2i;
        s_zs = ((red[0][0] + red[0][1]) + (red[0][2] + red[0][3]))
             + ((red[0][4] + red[0][5]) + (red[0][6] + red[0][7]));
        float E1 = row[c1];
        float ci = g_colinv[c1];
        float wr = (E1 * ci) / (g_colmaxE[c1] * ci + 1e-8f);
        s_wr = wr;
        atomicAdd(&g_denom[c1], wr);
    }
    __syncthreads();
    int gg1 = s_g1, gg2 = s_g2;
    float invZ = 1.0f / s_zs;
    float wr = s_wr;

    __half2* smh2 = (__half2*)(g_sm_h + (size_t)n * MP);
    for (int m4 = tid; m4 < 500; m4 += 256) {
        float4 e = ((const float4*)row)[m4];
        float4 sm4 = make_float4(e.x * invZ, e.y * invZ, e.z * invZ, e.w * invZ);
        ((float4*)Sr)[m4] = sm4;
        float4 ci = ((const float4*)g_colinv)[m4];
        ((float4*)Er)[m4] = make_float4(e.x * ci.x, e.y * ci.y, e.z * ci.z, e.w * ci.w);
        smh2[m4 * 2]     = __floats2half2_rn(sm4.x, sm4.y);
        smh2[m4 * 2 + 1] = __floats2half2_rn(sm4.z, sm4.w);
    }
    if (tid < 24) smh2[1000 + tid] = __floats2half2_rn(0.f, 0.f);

    float c2 = 0.f, p2s = 0.f, n2s = 0.f;
    const float* k1 = keys + (size_t)gg1 * 512;
    const float* k2 = keys + (size_t)gg2 * 512;
    float* dst = g_qupd + (size_t)gg1 * 512;
    for (int d = tid; d < 512; d += 256) {
        float qv = qrow[d];
        float df = qv - k1[d];           c2 += df * df;
        float dp = df + 1e-6f;           p2s += dp * dp;
        float dn = (qv - k2[d]) + 1e-6f; n2s += dn * dn;
        atomicAdd(&dst[d], wr * qv);
    }
    #pragma unroll
    for (int off = 16; off > 0; off >>= 1) {
        c2  += __shfl_down_sync(~0u, c2,  off);
        p2s += __shfl_down_sync(~0u, p2s, off);
        n2s += __shfl_down_sync(~0u, n2s, off);
    }
    if (lane == 0) { red[1][w] = c2; red[2][w] = p2s; red[3][w] = n2s; }
    __syncthreads();
    if (tid == 0) {
        c2 = p2s = n2s = 0.f;
        #pragma unroll
        for (int k = 0; k < 8; k++) { c2 += red[1][k]; p2s += red[2][k]; n2s += red[3][k]; }
        atomicAdd(&g_loss[0], fmaxf(sqrtf(p2s) - sqrtf(n2s) + 1.0f, 0.0f));
        atomicAdd(&g_loss[1], c2);
    }
}

// ---------------- K8: updated_memory (+ finalize losses) ---------------------
__global__ void k_umem(float* __restrict__ outb, const float* __restrict__ keys) {
    int m = blockIdx.x, tid = threadIdx.x;
    __shared__ float red[256];
    float dninv = 1.0f / (g_denom[m] + 1e-8f);
    float a0 = g_qupd[(size_t)m * 512 + tid]       * dninv + keys[(size_t)m * 512 + tid];
    float a1 = g_qupd[(size_t)m * 512 + tid + 256] * dninv + keys[(size_t)m * 512 + tid + 256];
    float s = block_reduce_sum256(a0 * a0 + a1 * a1, red);
    float inv = 1.0f / fmaxf(sqrtf(s), 1e-12f);
    float* um = outb + UM_OFF + (size_t)m * 512;
    um[tid] = a0 * inv; um[tid + 256] = a1 * inv;
    if (m == 0 && tid == 0) {
        outb[LS_OFF]     = g_loss[0] * (1.0f / 16384.0f);
        outb[LS_OFF + 1] = g_loss[1] * (1.0f / 8388608.0f);
    }
}

// ---------------- launch ------------------------------------------------------
extern "C" void kernel_launch(void* const* d_in, const int* in_sizes, int n_in,
                              void* d_out, int out_size) {
    const float* q    = (const float*)d_in[0];
    const float* keys = (const float*)d_in[1];
    float* out = (float*)d_out;

    const int PREP_SM = 32 * 521 * 4;             // 66688
    const int SM0 = 2 * 3 * MATB;                 // 61440
    const int SM1 = 2 * 2 * MATB;                 // 40960
    cudaFuncSetAttribute(k_prep,         cudaFuncAttributeMaxDynamicSharedMemorySize, PREP_SM);
    cudaFuncSetAttribute(k_mma<512, 0>,  cudaFuncAttributeMaxDynamicSharedMemorySize, SM0);
    cudaFuncSetAttribute(k_mma<2048, 1>, cudaFuncAttributeMaxDynamicSharedMemorySize, SM1);

    k_zero<<<1024, 256>>>();
    k_prep<<<dim3(32, 16), 256, PREP_SM>>>(q, out);
    k_keynorm<<<2000, 256>>>(keys);
    k_mma<512, 0><<<dim3(128, 16), 256, SM0>>>(out);      // 4th launch -> ncu capture slot
    k_colinv<<<8, 256>>>();
    k_rows2<<<16384, 256>>>(out, keys);
    k_keyT<<<dim3(64, 16), dim3(32, 8)>>>(keys);
    k_umem<<<2000, 256>>>(out, keys);
    k_mma<2048, 1><<<dim3(128, 4), 256, SM1>>>(out);
}